// round 8
// baseline (speedup 1.0000x reference)
#include <cuda_runtime.h>
#include <cuda_fp16.h>
#include <cstdint>

// ---------------------------------------------------------------------------
// GCNEncoder: 8-layer GCN, N=100000, E=1.6M, F=15->64(x7)->64
// h fp16; mid/final transforms = HMMA (fp32 accum); agg = CSR gather with
// block-cooperative smem staging of edge lists (contiguous CSR range/block).
// Preprocess: init(+wconv) -> edge_deg -> single-kernel lookback scan(+dinv)
// -> fill.  edge_index is int32 on device (JAX default, x64 disabled).
// ---------------------------------------------------------------------------

#define MAXN 131072
#define MAXE 1700000

__device__ __half g_t[MAXN * 64];        // transformed features (fp16)
__device__ __half g_hh[MAXN * 64];       // activations (fp16)
__device__ __half g_wh[7 * 4096];        // fp16 weights: Wm[0..5], Wl
__device__ float  g_deg[MAXN];
__device__ float  g_dinv[MAXN];
__device__ float  g_selfnorm[MAXN];
__device__ int    g_cnt[MAXN];
__device__ int    g_cursor[MAXN];
__device__ int    g_rowoff[MAXN + 1];
__device__ int    g_blkagg[128];
__device__ int    g_blkincl[128];
__device__ int    g_flag[128];
__device__ int    g_esrc[MAXE];
__device__ float  g_enorm[MAXE];

// ------------------------------ preprocessing ------------------------------

__global__ void k_init(const float* __restrict__ Wm,
                       const float* __restrict__ Wl, int N) {
    int i = blockIdx.x * blockDim.x + threadIdx.x;
    if (i < N) {
        g_deg[i] = 1.0f;   // self-loop weight
        g_cnt[i] = 0;
        g_cursor[i] = 0;
    }
    if (i < 128) g_flag[i] = 0;
    if (i < 6 * 4096)      g_wh[i] = __float2half(Wm[i]);
    else if (i < 7 * 4096) g_wh[i] = __float2half(Wl[i - 6 * 4096]);
}

__global__ void k_edge_deg(const int* __restrict__ ei,
                           const float* __restrict__ ew, int E, int N) {
    int i = blockIdx.x * blockDim.x + threadIdx.x;
    if (i >= E) return;
    int d = ei[E + i];
    if ((unsigned)d >= (unsigned)N) return;
    atomicAdd(&g_deg[d], ew[i]);
    atomicAdd(&g_cnt[d], 1);
}

// single-kernel: dinv/selfnorm + exclusive scan of g_cnt (decoupled lookback).
// grid = NB (<=128) blocks, all resident; 256 thr, 4 nodes/thread.
__global__ void k_scan(int N, int E, int NB) {
    int b = blockIdx.x;
    int t = threadIdx.x;
    int g0 = b * 1024 + 4 * t;

#pragma unroll
    for (int k = 0; k < 4; k++) {
        int g = g0 + k;
        if (g < N) {
            float dg = g_deg[g];
            float r = (dg > 0.0f) ? rsqrtf(dg) : 0.0f;
            g_dinv[g] = r;
            g_selfnorm[g] = r * r;
        }
    }

    int v0 = (g0 + 0 < N) ? g_cnt[g0 + 0] : 0;
    int v1 = (g0 + 1 < N) ? g_cnt[g0 + 1] : 0;
    int v2 = (g0 + 2 < N) ? g_cnt[g0 + 2] : 0;
    int v3 = (g0 + 3 < N) ? g_cnt[g0 + 3] : 0;
    int s = v0 + v1 + v2 + v3;
    int lane = t & 31, wid = t >> 5;
    int incl = s;
#pragma unroll
    for (int o = 1; o < 32; o <<= 1) {
        int x = __shfl_up_sync(0xffffffffu, incl, o);
        if (lane >= o) incl += x;
    }
    __shared__ int wsum[8];
    __shared__ int woff[8];
    __shared__ int sbase;
    if (lane == 31) wsum[wid] = incl;
    __syncthreads();
    if (t == 0) {
        int run = 0;
        for (int i = 0; i < 8; i++) { int x = wsum[i]; woff[i] = run; run += x; }
        int total = run;
        volatile int* vf = (volatile int*)g_flag;
        if (b == 0) {
            g_blkincl[0] = total;
            __threadfence();
            vf[0] = 2;
            sbase = 0;
        } else {
            g_blkagg[b] = total;
            __threadfence();
            vf[b] = 1;
            int acc = 0, p = b - 1;
            while (true) {
                int f;
                do { f = vf[p]; } while (f == 0);
                __threadfence();
                if (f == 2) { acc += g_blkincl[p]; break; }
                acc += g_blkagg[p];
                p--;
            }
            g_blkincl[b] = acc + total;
            __threadfence();
            vf[b] = 2;
            sbase = acc;
        }
        if (b == NB - 1) g_rowoff[N] = E;
    }
    __syncthreads();

    int excl = sbase + woff[wid] + (incl - s);
    if (g0 + 0 < N) g_rowoff[g0 + 0] = excl;
    if (g0 + 1 < N) g_rowoff[g0 + 1] = excl + v0;
    if (g0 + 2 < N) g_rowoff[g0 + 2] = excl + v0 + v1;
    if (g0 + 3 < N) g_rowoff[g0 + 3] = excl + v0 + v1 + v2;
}

__global__ void k_fill(const int* __restrict__ ei,
                       const float* __restrict__ ew, int E, int N) {
    int i = blockIdx.x * blockDim.x + threadIdx.x;
    if (i >= E) return;
    int s = ei[i];
    int d = ei[E + i];
    if ((unsigned)s >= (unsigned)N || (unsigned)d >= (unsigned)N) return;
    float nm = g_dinv[s] * ew[i] * g_dinv[d];
    int pos = g_rowoff[d] + atomicAdd(&g_cursor[d], 1);
    if ((unsigned)pos < (unsigned)MAXE) {
        g_esrc[pos] = s;
        g_enorm[pos] = nm;
    }
}

// ------------------------- layer-0 transform (SIMT) -------------------------
// C[N,64] = x[N,15] @ W0[15,64], fp32 compute, fp16 store.

__global__ void k_transform0(const float* __restrict__ A,
                             const float* __restrict__ W,
                             __half* __restrict__ C, int N) {
    __shared__ float As[15][68];
    __shared__ float Bs[15][68];
    int t = threadIdx.x;                 // 256 threads
    int n0 = blockIdx.x * 64;

    for (int idx = t; idx < 15 * 64; idx += 256) {
        int k = idx >> 6, f = idx & 63;
        Bs[k][f] = W[idx];
    }
    for (int idx = t; idx < 64 * 15; idx += 256) {
        int node = idx / 15;
        int k = idx % 15;
        int gn = n0 + node;
        As[k][node] = (gn < N) ? A[(size_t)gn * 15 + k] : 0.f;
    }
    __syncthreads();

    int tx = t & 15, ty = t >> 4;
    float acc[4][4];
#pragma unroll
    for (int i = 0; i < 4; i++)
#pragma unroll
        for (int j = 0; j < 4; j++) acc[i][j] = 0.f;

#pragma unroll
    for (int k = 0; k < 15; k++) {
        float4 a = *(const float4*)&As[k][4 * ty];
        float4 b = *(const float4*)&Bs[k][4 * tx];
        float av[4] = {a.x, a.y, a.z, a.w};
        float bv[4] = {b.x, b.y, b.z, b.w};
#pragma unroll
        for (int i = 0; i < 4; i++)
#pragma unroll
            for (int j = 0; j < 4; j++) acc[i][j] += av[i] * bv[j];
    }

#pragma unroll
    for (int i = 0; i < 4; i++) {
        int gn = n0 + 4 * ty + i;
        if (gn < N) {
            __half2 p0 = __floats2half2_rn(acc[i][0], acc[i][1]);
            __half2 p1 = __floats2half2_rn(acc[i][2], acc[i][3]);
            uint2 pk;
            pk.x = *(unsigned*)&p0;
            pk.y = *(unsigned*)&p1;
            *(uint2*)(C + (size_t)gn * 64 + 4 * tx) = pk;
        }
    }
}

// ---------------------- mid/final transform (tensor core) -------------------
// C[N,64] = A[N,64] @ W[64,64]; A,W fp16, fp32 accum via mma.m16n8k16.

__device__ __forceinline__ void mma16816(float c[4], unsigned a0, unsigned a1,
                                         unsigned a2, unsigned a3,
                                         unsigned b0, unsigned b1) {
    asm volatile(
        "mma.sync.aligned.m16n8k16.row.col.f32.f16.f16.f32 "
        "{%0,%1,%2,%3}, {%4,%5,%6,%7}, {%8,%9}, {%0,%1,%2,%3};\n"
        : "+f"(c[0]), "+f"(c[1]), "+f"(c[2]), "+f"(c[3])
        : "r"(a0), "r"(a1), "r"(a2), "r"(a3), "r"(b0), "r"(b1));
}

__global__ void __launch_bounds__(256) k_transform_tc(
    const __half* __restrict__ A,      // [N,64] fp16
    const __half* __restrict__ Wh,     // [64,64] fp16, k-major
    __half* __restrict__ C, int N)
{
    __shared__ __align__(16) __half As[128 * 72];   // row stride 72 halves
    __shared__ __align__(16) __half Wt[64 * 72];    // transposed [n][k]

    int tid = threadIdx.x;
    int n0 = blockIdx.x * 128;

    for (int i = tid; i < 4096; i += 256) {
        int k = i >> 6, n = i & 63;
        Wt[n * 72 + k] = Wh[i];
    }
    {
        const uint4* Ag = (const uint4*)A;   // 8 uint4 per 64-half row
#pragma unroll
        for (int r4 = 0; r4 < 4; r4++) {
            int q = tid + 256 * r4;          // 0..1023
            int r = q >> 3, u = q & 7;
            int gr = n0 + r;
            uint4 v = (gr < N) ? Ag[(size_t)gr * 8 + u]
                               : make_uint4(0u, 0u, 0u, 0u);
            *(uint4*)&As[r * 72 + u * 8] = v;
        }
    }
    __syncthreads();

    int lane = tid & 31, warp = tid >> 5;
    int g = lane >> 2, t = lane & 3;
    int m0 = warp * 16;

    float acc[8][4];
#pragma unroll
    for (int i = 0; i < 8; i++)
#pragma unroll
        for (int j = 0; j < 4; j++) acc[i][j] = 0.f;

    const unsigned* As2 = (const unsigned*)As;   // stride 36 uints
    const unsigned* Wt2 = (const unsigned*)Wt;

#pragma unroll
    for (int ks = 0; ks < 4; ks++) {
        int k8 = ks * 8;                         // k offset in uints
        unsigned a0 = As2[(m0 + g) * 36 + k8 + t];
        unsigned a1 = As2[(m0 + g + 8) * 36 + k8 + t];
        unsigned a2 = As2[(m0 + g) * 36 + k8 + 4 + t];
        unsigned a3 = As2[(m0 + g + 8) * 36 + k8 + 4 + t];
#pragma unroll
        for (int nt = 0; nt < 8; nt++) {
            unsigned b0 = Wt2[(nt * 8 + g) * 36 + k8 + t];
            unsigned b1 = Wt2[(nt * 8 + g) * 36 + k8 + 4 + t];
            mma16816(acc[nt], a0, a1, a2, a3, b0, b1);
        }
    }

    __half2* Cv = (__half2*)C;                   // 32 half2 per row
    int r0 = n0 + m0 + g;
    int r1 = r0 + 8;
#pragma unroll
    for (int nt = 0; nt < 8; nt++) {
        if (r0 < N) Cv[(size_t)r0 * 32 + nt * 4 + t] =
            __floats2half2_rn(acc[nt][0], acc[nt][1]);
        if (r1 < N) Cv[(size_t)r1 * 32 + nt * 4 + t] =
            __floats2half2_rn(acc[nt][2], acc[nt][3]);
    }
}

// ------------------------------- aggregation -------------------------------
// Block = 8 warps = 8 consecutive nodes; the block's CSR segments form one
// contiguous edge range -> coalesced staging into smem, then each warp's hot
// loop is LDS(broadcast) + gather only. Fallback to gmem loop if >1024 edges.

template <bool FP16OUT>
__global__ void __launch_bounds__(256) k_agg(
    const __half2* __restrict__ tin,
    const float* __restrict__ bias,
    void* __restrict__ outp, int N, int act)
{
    __shared__ int   sIdx[1024];
    __shared__ float sNrm[1024];

    int tid = threadIdx.x, lane = tid & 31, wid = tid >> 5;
    int nb = blockIdx.x * 8;
    int lastNode = min(nb + 8, N);
    int first = g_rowoff[nb];
    int last  = g_rowoff[lastNode];
    int cnt = last - first;
    bool staged = (cnt <= 1024);

    if (staged) {
        for (int i = tid; i < cnt; i += 256) {
            sIdx[i] = g_esrc[first + i];
            sNrm[i] = g_enorm[first + i];
        }
    }
    __syncthreads();

    int w = nb + wid;
    if (w >= N) return;

    float2 self = __half22float2(tin[(size_t)w * 32 + lane]);
    float sn = g_selfnorm[w];
    float ax = sn * self.x;
    float ay = sn * self.y;
    float bx = 0.f, by = 0.f;

    int beg = g_rowoff[w];
    int end = g_rowoff[w + 1];

    if (staged) {
        int j = beg - first, je = end - first;
        for (; j + 4 <= je; j += 4) {
            int s0 = sIdx[j + 0], s1 = sIdx[j + 1];
            int s2 = sIdx[j + 2], s3 = sIdx[j + 3];
            float m0 = sNrm[j + 0], m1 = sNrm[j + 1];
            float m2 = sNrm[j + 2], m3 = sNrm[j + 3];
            float2 v0 = __half22float2(tin[(size_t)s0 * 32 + lane]);
            float2 v1 = __half22float2(tin[(size_t)s1 * 32 + lane]);
            float2 v2 = __half22float2(tin[(size_t)s2 * 32 + lane]);
            float2 v3 = __half22float2(tin[(size_t)s3 * 32 + lane]);
            ax += m0 * v0.x; ay += m0 * v0.y;
            bx += m1 * v1.x; by += m1 * v1.y;
            ax += m2 * v2.x; ay += m2 * v2.y;
            bx += m3 * v3.x; by += m3 * v3.y;
        }
        for (; j < je; j++) {
            int s = sIdx[j];
            float m = sNrm[j];
            float2 v = __half22float2(tin[(size_t)s * 32 + lane]);
            ax += m * v.x; ay += m * v.y;
        }
    } else {
        for (int j = beg; j < end; j++) {
            int s = g_esrc[j];
            float m = g_enorm[j];
            float2 v = __half22float2(tin[(size_t)s * 32 + lane]);
            ax += m * v.x; ay += m * v.y;
        }
    }
    ax += bx; ay += by;

    float2 b = ((const float2*)bias)[lane];
    ax += b.x; ay += b.y;
    if (act == 1) {
        ax = fmaxf(ax, 0.f);
        ay = fmaxf(ay, 0.f);
    } else {
        ax = 1.0f / (1.0f + __expf(-ax));
        ay = 1.0f / (1.0f + __expf(-ay));
    }
    if (FP16OUT) {
        ((__half2*)outp)[(size_t)w * 32 + lane] = __floats2half2_rn(ax, ay);
    } else {
        ((float2*)outp)[(size_t)w * 32 + lane] = make_float2(ax, ay);
    }
}

// --------------------------------- launcher --------------------------------

extern "C" void kernel_launch(void* const* d_in, const int* in_sizes, int n_in,
                              void* d_out, int out_size) {
    const float* x  = (const float*)d_in[0];
    const int*   ei = (const int*)d_in[1];     // int32 (JAX default, x64 off)
    const float* ew = (const float*)d_in[2];
    const float* W0 = (const float*)d_in[3];
    const float* b0 = (const float*)d_in[4];
    const float* Wm = (const float*)d_in[5];
    const float* bm = (const float*)d_in[6];
    const float* Wl = (const float*)d_in[7];
    const float* bl = (const float*)d_in[8];

    int N = in_sizes[0] / 15;
    int E = in_sizes[2];

    __half* t;
    __half* h;
    __half* wh;
    cudaGetSymbolAddress((void**)&t, g_t);
    cudaGetSymbolAddress((void**)&h, g_hh);
    cudaGetSymbolAddress((void**)&wh, g_wh);

    int NB = (N + 1023) / 1024;

    k_init<<<(N + 255) / 256, 256>>>(Wm, Wl, N);
    k_edge_deg<<<(E + 255) / 256, 256>>>(ei, ew, E, N);
    k_scan<<<NB, 256>>>(N, E, NB);
    k_fill<<<(E + 255) / 256, 256>>>(ei, ew, E, N);

    int gT = (N + 127) / 128;
    int gA = (N + 7) / 8;

    // layer 0: h = relu(agg(x @ W0) + b0)
    k_transform0<<<(N + 63) / 64, 256>>>(x, W0, t, N);
    k_agg<true><<<gA, 256>>>((const __half2*)t, b0, h, N, 1);

    // middle layers 1..6 (tensor-core transform)
    for (int i = 0; i < 6; i++) {
        k_transform_tc<<<gT, 256>>>(h, wh + (size_t)i * 4096, t, N);
        k_agg<true><<<gA, 256>>>((const __half2*)t, bm + (size_t)i * 64, h, N, 1);
    }

    // final layer + sigmoid -> d_out (fp32)
    k_transform_tc<<<gT, 256>>>(h, wh + (size_t)6 * 4096, t, N);
    k_agg<false><<<gA, 256>>>((const __half2*)t, bl, d_out, N, 2);
}

// round 9
// speedup vs baseline: 1.0784x; 1.0784x over previous
#include <cuda_runtime.h>
#include <cuda_fp16.h>
#include <cstdint>

// ---------------------------------------------------------------------------
// GCNEncoder: 8-layer GCN, N=100000, E=1.6M, F=15->64(x7)->64
// h fp16; mid/final transforms = HMMA (fp32 accum).
// agg = one warp/node CSR gather; edge list stored as interleaved (src,norm)
// 8B pairs -> 1 uniform int4 per 2 edges + 2 coalesced row gathers.
// Preprocess: init(+wconv) -> edge_deg -> lookback scan(+dinv) -> fill.
// edge_index is int32 on device (JAX default, x64 disabled).
// ---------------------------------------------------------------------------

#define MAXN 131072
#define MAXE 1700000

__device__ __half g_t[MAXN * 64];        // transformed features (fp16)
__device__ __half g_hh[MAXN * 64];       // activations (fp16)
__device__ __half g_wh[7 * 4096];        // fp16 weights: Wm[0..5], Wl
__device__ float  g_deg[MAXN];
__device__ float  g_dinv[MAXN];
__device__ float  g_selfnorm[MAXN];
__device__ int    g_cnt[MAXN];
__device__ int    g_cursor[MAXN];
__device__ int    g_rowoff[MAXN + 1];
__device__ int    g_blkagg[128];
__device__ int    g_blkincl[128];
__device__ int    g_flag[128];
__device__ __align__(16) unsigned long long g_epair[MAXE];  // (norm<<32)|src

// ------------------------------ preprocessing ------------------------------

__global__ void k_init(const float* __restrict__ Wm,
                       const float* __restrict__ Wl, int N) {
    int i = blockIdx.x * blockDim.x + threadIdx.x;
    if (i < N) {
        g_deg[i] = 1.0f;   // self-loop weight
        g_cnt[i] = 0;
        g_cursor[i] = 0;
    }
    if (i < 128) g_flag[i] = 0;
    if (i < 6 * 4096)      g_wh[i] = __float2half(Wm[i]);
    else if (i < 7 * 4096) g_wh[i] = __float2half(Wl[i - 6 * 4096]);
}

__global__ void k_edge_deg(const int* __restrict__ ei,
                           const float* __restrict__ ew, int E, int N) {
    int i = blockIdx.x * blockDim.x + threadIdx.x;
    if (i >= E) return;
    int d = ei[E + i];
    if ((unsigned)d >= (unsigned)N) return;
    atomicAdd(&g_deg[d], ew[i]);
    atomicAdd(&g_cnt[d], 1);
}

// single-kernel: dinv/selfnorm + exclusive scan of g_cnt (decoupled lookback).
__global__ void k_scan(int N, int E, int NB) {
    int b = blockIdx.x;
    int t = threadIdx.x;
    int g0 = b * 1024 + 4 * t;

#pragma unroll
    for (int k = 0; k < 4; k++) {
        int g = g0 + k;
        if (g < N) {
            float dg = g_deg[g];
            float r = (dg > 0.0f) ? rsqrtf(dg) : 0.0f;
            g_dinv[g] = r;
            g_selfnorm[g] = r * r;
        }
    }

    int v0 = (g0 + 0 < N) ? g_cnt[g0 + 0] : 0;
    int v1 = (g0 + 1 < N) ? g_cnt[g0 + 1] : 0;
    int v2 = (g0 + 2 < N) ? g_cnt[g0 + 2] : 0;
    int v3 = (g0 + 3 < N) ? g_cnt[g0 + 3] : 0;
    int s = v0 + v1 + v2 + v3;
    int lane = t & 31, wid = t >> 5;
    int incl = s;
#pragma unroll
    for (int o = 1; o < 32; o <<= 1) {
        int x = __shfl_up_sync(0xffffffffu, incl, o);
        if (lane >= o) incl += x;
    }
    __shared__ int wsum[8];
    __shared__ int woff[8];
    __shared__ int sbase;
    if (lane == 31) wsum[wid] = incl;
    __syncthreads();
    if (t == 0) {
        int run = 0;
        for (int i = 0; i < 8; i++) { int x = wsum[i]; woff[i] = run; run += x; }
        int total = run;
        volatile int* vf = (volatile int*)g_flag;
        if (b == 0) {
            g_blkincl[0] = total;
            __threadfence();
            vf[0] = 2;
            sbase = 0;
        } else {
            g_blkagg[b] = total;
            __threadfence();
            vf[b] = 1;
            int acc = 0, p = b - 1;
            while (true) {
                int f;
                do { f = vf[p]; } while (f == 0);
                __threadfence();
                if (f == 2) { acc += g_blkincl[p]; break; }
                acc += g_blkagg[p];
                p--;
            }
            g_blkincl[b] = acc + total;
            __threadfence();
            vf[b] = 2;
            sbase = acc;
        }
        if (b == NB - 1) g_rowoff[N] = E;
    }
    __syncthreads();

    int excl = sbase + woff[wid] + (incl - s);
    if (g0 + 0 < N) g_rowoff[g0 + 0] = excl;
    if (g0 + 1 < N) g_rowoff[g0 + 1] = excl + v0;
    if (g0 + 2 < N) g_rowoff[g0 + 2] = excl + v0 + v1;
    if (g0 + 3 < N) g_rowoff[g0 + 3] = excl + v0 + v1 + v2;
}

__global__ void k_fill(const int* __restrict__ ei,
                       const float* __restrict__ ew, int E, int N) {
    int i = blockIdx.x * blockDim.x + threadIdx.x;
    if (i >= E) return;
    int s = ei[i];
    int d = ei[E + i];
    if ((unsigned)s >= (unsigned)N || (unsigned)d >= (unsigned)N) return;
    float nm = g_dinv[s] * ew[i] * g_dinv[d];
    int pos = g_rowoff[d] + atomicAdd(&g_cursor[d], 1);
    if ((unsigned)pos < (unsigned)MAXE) {
        unsigned long long pr =
            ((unsigned long long)__float_as_uint(nm) << 32) | (unsigned)s;
        g_epair[pos] = pr;
    }
}

// ------------------------- layer-0 transform (SIMT) -------------------------
// C[N,64] = x[N,15] @ W0[15,64], fp32 compute, fp16 store.

__global__ void k_transform0(const float* __restrict__ A,
                             const float* __restrict__ W,
                             __half* __restrict__ C, int N) {
    __shared__ float As[15][68];
    __shared__ float Bs[15][68];
    int t = threadIdx.x;                 // 256 threads
    int n0 = blockIdx.x * 64;

    for (int idx = t; idx < 15 * 64; idx += 256) {
        int k = idx >> 6, f = idx & 63;
        Bs[k][f] = W[idx];
    }
    for (int idx = t; idx < 64 * 15; idx += 256) {
        int node = idx / 15;
        int k = idx % 15;
        int gn = n0 + node;
        As[k][node] = (gn < N) ? A[(size_t)gn * 15 + k] : 0.f;
    }
    __syncthreads();

    int tx = t & 15, ty = t >> 4;
    float acc[4][4];
#pragma unroll
    for (int i = 0; i < 4; i++)
#pragma unroll
        for (int j = 0; j < 4; j++) acc[i][j] = 0.f;

#pragma unroll
    for (int k = 0; k < 15; k++) {
        float4 a = *(const float4*)&As[k][4 * ty];
        float4 b = *(const float4*)&Bs[k][4 * tx];
        float av[4] = {a.x, a.y, a.z, a.w};
        float bv[4] = {b.x, b.y, b.z, b.w};
#pragma unroll
        for (int i = 0; i < 4; i++)
#pragma unroll
            for (int j = 0; j < 4; j++) acc[i][j] += av[i] * bv[j];
    }

#pragma unroll
    for (int i = 0; i < 4; i++) {
        int gn = n0 + 4 * ty + i;
        if (gn < N) {
            __half2 p0 = __floats2half2_rn(acc[i][0], acc[i][1]);
            __half2 p1 = __floats2half2_rn(acc[i][2], acc[i][3]);
            uint2 pk;
            pk.x = *(unsigned*)&p0;
            pk.y = *(unsigned*)&p1;
            *(uint2*)(C + (size_t)gn * 64 + 4 * tx) = pk;
        }
    }
}

// ---------------------- mid/final transform (tensor core) -------------------
// C[N,64] = A[N,64] @ W[64,64]; A,W fp16, fp32 accum via mma.m16n8k16.

__device__ __forceinline__ void mma16816(float c[4], unsigned a0, unsigned a1,
                                         unsigned a2, unsigned a3,
                                         unsigned b0, unsigned b1) {
    asm volatile(
        "mma.sync.aligned.m16n8k16.row.col.f32.f16.f16.f32 "
        "{%0,%1,%2,%3}, {%4,%5,%6,%7}, {%8,%9}, {%0,%1,%2,%3};\n"
        : "+f"(c[0]), "+f"(c[1]), "+f"(c[2]), "+f"(c[3])
        : "r"(a0), "r"(a1), "r"(a2), "r"(a3), "r"(b0), "r"(b1));
}

__global__ void __launch_bounds__(256) k_transform_tc(
    const __half* __restrict__ A,      // [N,64] fp16
    const __half* __restrict__ Wh,     // [64,64] fp16, k-major
    __half* __restrict__ C, int N)
{
    __shared__ __align__(16) __half As[128 * 72];   // row stride 72 halves
    __shared__ __align__(16) __half Wt[64 * 72];    // transposed [n][k]

    int tid = threadIdx.x;
    int n0 = blockIdx.x * 128;

    for (int i = tid; i < 4096; i += 256) {
        int k = i >> 6, n = i & 63;
        Wt[n * 72 + k] = Wh[i];
    }
    {
        const uint4* Ag = (const uint4*)A;   // 8 uint4 per 64-half row
#pragma unroll
        for (int r4 = 0; r4 < 4; r4++) {
            int q = tid + 256 * r4;          // 0..1023
            int r = q >> 3, u = q & 7;
            int gr = n0 + r;
            uint4 v = (gr < N) ? Ag[(size_t)gr * 8 + u]
                               : make_uint4(0u, 0u, 0u, 0u);
            *(uint4*)&As[r * 72 + u * 8] = v;
        }
    }
    __syncthreads();

    int lane = tid & 31, warp = tid >> 5;
    int g = lane >> 2, t = lane & 3;
    int m0 = warp * 16;

    float acc[8][4];
#pragma unroll
    for (int i = 0; i < 8; i++)
#pragma unroll
        for (int j = 0; j < 4; j++) acc[i][j] = 0.f;

    const unsigned* As2 = (const unsigned*)As;   // stride 36 uints
    const unsigned* Wt2 = (const unsigned*)Wt;

#pragma unroll
    for (int ks = 0; ks < 4; ks++) {
        int k8 = ks * 8;                         // k offset in uints
        unsigned a0 = As2[(m0 + g) * 36 + k8 + t];
        unsigned a1 = As2[(m0 + g + 8) * 36 + k8 + t];
        unsigned a2 = As2[(m0 + g) * 36 + k8 + 4 + t];
        unsigned a3 = As2[(m0 + g + 8) * 36 + k8 + 4 + t];
#pragma unroll
        for (int nt = 0; nt < 8; nt++) {
            unsigned b0 = Wt2[(nt * 8 + g) * 36 + k8 + t];
            unsigned b1 = Wt2[(nt * 8 + g) * 36 + k8 + 4 + t];
            mma16816(acc[nt], a0, a1, a2, a3, b0, b1);
        }
    }

    __half2* Cv = (__half2*)C;                   // 32 half2 per row
    int r0 = n0 + m0 + g;
    int r1 = r0 + 8;
#pragma unroll
    for (int nt = 0; nt < 8; nt++) {
        if (r0 < N) Cv[(size_t)r0 * 32 + nt * 4 + t] =
            __floats2half2_rn(acc[nt][0], acc[nt][1]);
        if (r1 < N) Cv[(size_t)r1 * 32 + nt * 4 + t] =
            __floats2half2_rn(acc[nt][2], acc[nt][3]);
    }
}

// ------------------------------- aggregation -------------------------------
// One warp per node; lane holds 2 features as one half2; fp32 accumulation.
// Edge list = interleaved (src,norm) pairs: 1 uniform int4 per 2 edges.

template <bool FP16OUT>
__global__ void k_agg(const __half2* __restrict__ tin,
                      const float* __restrict__ bias,
                      void* __restrict__ outp, int N, int act) {
    int w = (blockIdx.x * blockDim.x + threadIdx.x) >> 5;
    int lane = threadIdx.x & 31;
    if (w >= N) return;

    float2 self = __half22float2(tin[(size_t)w * 32 + lane]);
    float sn = g_selfnorm[w];
    float ax = sn * self.x;
    float ay = sn * self.y;
    float bx = 0.f, by = 0.f;

    int beg = g_rowoff[w];
    int end = g_rowoff[w + 1];
    int j = beg;

    // peel one edge if start is odd (int4 needs 16B = 2-pair alignment)
    if ((j & 1) && j < end) {
        unsigned long long p = g_epair[j];
        int s = (int)(unsigned)p;
        float m = __uint_as_float((unsigned)(p >> 32));
        float2 v = __half22float2(tin[(size_t)s * 32 + lane]);
        ax += m * v.x; ay += m * v.y;
        j++;
    }
    // 2 edges per uniform int4
    for (; j + 2 <= end; j += 2) {
        int4 pr = *(const int4*)&g_epair[j];
        int s0 = pr.x;
        float m0 = __int_as_float(pr.y);
        int s1 = pr.z;
        float m1 = __int_as_float(pr.w);
        float2 v0 = __half22float2(tin[(size_t)s0 * 32 + lane]);
        float2 v1 = __half22float2(tin[(size_t)s1 * 32 + lane]);
        ax += m0 * v0.x; ay += m0 * v0.y;
        bx += m1 * v1.x; by += m1 * v1.y;
    }
    // tail edge
    if (j < end) {
        unsigned long long p = g_epair[j];
        int s = (int)(unsigned)p;
        float m = __uint_as_float((unsigned)(p >> 32));
        float2 v = __half22float2(tin[(size_t)s * 32 + lane]);
        ax += m * v.x; ay += m * v.y;
    }
    ax += bx; ay += by;

    float2 b = ((const float2*)bias)[lane];
    ax += b.x; ay += b.y;
    if (act == 1) {
        ax = fmaxf(ax, 0.f);
        ay = fmaxf(ay, 0.f);
    } else {
        ax = 1.0f / (1.0f + __expf(-ax));
        ay = 1.0f / (1.0f + __expf(-ay));
    }
    if (FP16OUT) {
        ((__half2*)outp)[(size_t)w * 32 + lane] = __floats2half2_rn(ax, ay);
    } else {
        ((float2*)outp)[(size_t)w * 32 + lane] = make_float2(ax, ay);
    }
}

// --------------------------------- launcher --------------------------------

extern "C" void kernel_launch(void* const* d_in, const int* in_sizes, int n_in,
                              void* d_out, int out_size) {
    const float* x  = (const float*)d_in[0];
    const int*   ei = (const int*)d_in[1];     // int32 (JAX default, x64 off)
    const float* ew = (const float*)d_in[2];
    const float* W0 = (const float*)d_in[3];
    const float* b0 = (const float*)d_in[4];
    const float* Wm = (const float*)d_in[5];
    const float* bm = (const float*)d_in[6];
    const float* Wl = (const float*)d_in[7];
    const float* bl = (const float*)d_in[8];

    int N = in_sizes[0] / 15;
    int E = in_sizes[2];

    __half* t;
    __half* h;
    __half* wh;
    cudaGetSymbolAddress((void**)&t, g_t);
    cudaGetSymbolAddress((void**)&h, g_hh);
    cudaGetSymbolAddress((void**)&wh, g_wh);

    int NB = (N + 1023) / 1024;

    k_init<<<(N + 255) / 256, 256>>>(Wm, Wl, N);
    k_edge_deg<<<(E + 255) / 256, 256>>>(ei, ew, E, N);
    k_scan<<<NB, 256>>>(N, E, NB);
    k_fill<<<(E + 255) / 256, 256>>>(ei, ew, E, N);

    int gT = (N + 127) / 128;
    int gA = (N + 7) / 8;

    // layer 0: h = relu(agg(x @ W0) + b0)
    k_transform0<<<(N + 63) / 64, 256>>>(x, W0, t, N);
    k_agg<true><<<gA, 256>>>((const __half2*)t, b0, h, N, 1);

    // middle layers 1..6 (tensor-core transform)
    for (int i = 0; i < 6; i++) {
        k_transform_tc<<<gT, 256>>>(h, wh + (size_t)i * 4096, t, N);
        k_agg<true><<<gA, 256>>>((const __half2*)t, bm + (size_t)i * 64, h, N, 1);
    }

    // final layer + sigmoid -> d_out (fp32)
    k_transform_tc<<<gT, 256>>>(h, wh + (size_t)6 * 4096, t, N);
    k_agg<false><<<gA, 256>>>((const __half2*)t, bl, d_out, N, 2);
}